// round 9
// baseline (speedup 1.0000x reference)
#include <cuda_runtime.h>
#include <cuda_fp16.h>
#include <float.h>
#include <math.h>

// CapsuleConv2d: B=2, Cin=128, H=W=32, weight [O=16,L=16,M=16,3,3]
// 1 CTA per (b,h,w), 128 threads, thread computes TWO columns: ol = tid, tid+128.
//  - priors (fp32 f32x2 FMA, 4 split chains) streamed to smem as half2(sA,sB) pairs
//  - routing passes read the SAME pair rows; PRMT extracts lo (pass A) / hi (pass B)
//  - per-iter cross-lane: 4 + 15 + 16 shfl within 16-lane groups
//  - launch_bounds(128,4): 4 CTAs/SM (64K regs, 170KB smem)

__device__ float4 g_wT4[9 * 4 * 256];  // [(p*4+q)*256 + ol] = W[ol][4q..4q+3][p]

__global__ void wt_transpose(const float* __restrict__ w) {
    int idx = blockIdx.x * 256 + threadIdx.x;   // 9216 total
    int p  = idx >> 10;
    int q  = (idx >> 8) & 3;
    int ol = idx & 255;
    g_wT4[idx] = make_float4(w[(ol * 16 + 4 * q + 0) * 9 + p],
                             w[(ol * 16 + 4 * q + 1) * 9 + p],
                             w[(ol * 16 + 4 * q + 2) * 9 + p],
                             w[(ol * 16 + 4 * q + 3) * 9 + p]);
}

__device__ __forceinline__ unsigned long long fma2(unsigned long long a,
                                                   unsigned long long b,
                                                   unsigned long long c) {
    unsigned long long d;
    asm("fma.rn.f32x2 %0, %1, %2, %3;" : "=l"(d) : "l"(a), "l"(b), "l"(c));
    return d;
}
__device__ __forceinline__ unsigned long long add2(unsigned long long a,
                                                   unsigned long long b) {
    unsigned long long d;
    asm("add.rn.f32x2 %0, %1, %2;" : "=l"(d) : "l"(a), "l"(b));
    return d;
}
__device__ __forceinline__ unsigned prmt(unsigned a, unsigned b, unsigned sel) {
    unsigned d;
    asm("prmt.b32 %0, %1, %2, %3;" : "=r"(d) : "r"(a), "r"(b), "r"(sel));
    return d;
}

#define USTRIDE_P 132   // row stride in half2 pairs (528 B): conflict-free phases

__global__ __launch_bounds__(128, 4)
void capsule_kernel(const float* __restrict__ x, float* __restrict__ out) {
    extern __shared__ __align__(16) float smem[];
    float* xs = smem;                                      // 9*128 patch (fp32)
    unsigned* su = reinterpret_cast<unsigned*>(smem + 1152); // 72 * USTRIDE_P pairs

    const unsigned FULL = 0xffffffffu;
    const int tid = threadIdx.x;     // colA = tid, colB = tid + 128
    const int lane = tid & 15;       // l
    const int grp = tid >> 4;        // o for colA (0..7); colB is grp+8
    const int bid = blockIdx.x;
    const int b = bid >> 10;
    const int h = (bid >> 5) & 31;
    const int w = bid & 31;

    // Stage 3x3 patch (zero-padded): 9 pixels x 128 channels
    for (int idx = tid; idx < 9 * 128; idx += 128) {
        int p = idx >> 7;
        int c = idx & 127;
        int hh = h + p / 3 - 1;
        int ww = w + p % 3 - 1;
        float v = 0.f;
        if ((unsigned)hh < 32u && (unsigned)ww < 32u)
            v = x[((b * 128 + c) * 32 + hh) * 32 + ww];
        xs[idx] = v;
    }
    __syncthreads();

    // ---- priors for BOTH columns; 4 split FMA chains per (p,g) ----
    float vmeanA = 0.f, vmeanB = 0.f;
    const ulonglong2* xs2 = reinterpret_cast<const ulonglong2*>(xs);
    const ulonglong2* wp = reinterpret_cast<const ulonglong2*>(g_wT4);
#pragma unroll
    for (int p = 0; p < 9; p++) {
        ulonglong2 wa0 = wp[(p * 4 + 0) * 256 + tid];
        ulonglong2 wa1 = wp[(p * 4 + 1) * 256 + tid];
        ulonglong2 wa2 = wp[(p * 4 + 2) * 256 + tid];
        ulonglong2 wa3 = wp[(p * 4 + 3) * 256 + tid];
        ulonglong2 wb0 = wp[(p * 4 + 0) * 256 + tid + 128];
        ulonglong2 wb1 = wp[(p * 4 + 1) * 256 + tid + 128];
        ulonglong2 wb2 = wp[(p * 4 + 2) * 256 + tid + 128];
        ulonglong2 wb3 = wp[(p * 4 + 3) * 256 + tid + 128];
#pragma unroll
        for (int g = 0; g < 8; g++) {
            ulonglong2 A  = xs2[p * 32 + g * 4 + 0];
            ulonglong2 Bq = xs2[p * 32 + g * 4 + 1];
            ulonglong2 C  = xs2[p * 32 + g * 4 + 2];
            ulonglong2 D  = xs2[p * 32 + g * 4 + 3];
            // two chains per column (even/odd 64-bit slices)
            unsigned long long a0 = fma2(A.x,  wa0.x, 0ull);
            unsigned long long a1 = fma2(A.y,  wa0.y, 0ull);
            unsigned long long b0 = fma2(A.x,  wb0.x, 0ull);
            unsigned long long b1 = fma2(A.y,  wb0.y, 0ull);
            a0 = fma2(Bq.x, wa1.x, a0);  a1 = fma2(Bq.y, wa1.y, a1);
            b0 = fma2(Bq.x, wb1.x, b0);  b1 = fma2(Bq.y, wb1.y, b1);
            a0 = fma2(C.x,  wa2.x, a0);  a1 = fma2(C.y,  wa2.y, a1);
            b0 = fma2(C.x,  wb2.x, b0);  b1 = fma2(C.y,  wb2.y, b1);
            a0 = fma2(D.x,  wa3.x, a0);  a1 = fma2(D.y,  wa3.y, a1);
            b0 = fma2(D.x,  wb3.x, b0);  b1 = fma2(D.y,  wb3.y, b1);
            unsigned long long sa = add2(a0, a1);
            unsigned long long sb = add2(b0, b1);
            float loA, hiA, loB, hiB;
            asm("mov.b64 {%0, %1}, %2;" : "=f"(loA), "=f"(hiA) : "l"(sa));
            asm("mov.b64 {%0, %1}, %2;" : "=f"(loB), "=f"(hiB) : "l"(sb));
            float sA = loA + hiA;
            float sB = loB + hiB;
            int n = g * 9 + p;
            __half2 pr = __floats2half2_rn(sA, sB);   // x = colA, y = colB
            su[n * USTRIDE_P + tid] = *reinterpret_cast<unsigned*>(&pr);
            vmeanA += sA;
            vmeanB += sB;
        }
    }
    __syncthreads();

    // ---- routing: two passes read SAME pair rows; PRMT selects lo/hi ----
#pragma unroll 1
    for (int pass = 0; pass < 2; pass++) {
        const int col = tid + pass * 128;
        const unsigned sel = pass ? 0x7632u : 0x5410u;   // hi : lo halves
        const float vmean = pass ? vmeanB : vmeanA;

        // rows2[j*8+i] = half2(u[16j+lane][colbase+2i], u[..][colbase+2i+1])
        __half2 rows2[40];
#pragma unroll
        for (int j = 0; j < 5; j++) {
            int n = 16 * j + lane;
            if (n >= 72) n -= 72;            // wrap; masked later (e4=0)
            const uint4* rp = reinterpret_cast<const uint4*>(su + n * USTRIDE_P + grp * 16);
            uint4 q0 = rp[0], q1 = rp[1], q2 = rp[2], q3 = rp[3];
            unsigned r0 = prmt(q0.x, q0.y, sel);
            unsigned r1 = prmt(q0.z, q0.w, sel);
            unsigned r2 = prmt(q1.x, q1.y, sel);
            unsigned r3 = prmt(q1.z, q1.w, sel);
            unsigned r4 = prmt(q2.x, q2.y, sel);
            unsigned r5 = prmt(q2.z, q2.w, sel);
            unsigned r6 = prmt(q3.x, q3.y, sel);
            unsigned r7 = prmt(q3.z, q3.w, sel);
            rows2[j * 8 + 0] = *reinterpret_cast<__half2*>(&r0);
            rows2[j * 8 + 1] = *reinterpret_cast<__half2*>(&r1);
            rows2[j * 8 + 2] = *reinterpret_cast<__half2*>(&r2);
            rows2[j * 8 + 3] = *reinterpret_cast<__half2*>(&r3);
            rows2[j * 8 + 4] = *reinterpret_cast<__half2*>(&r4);
            rows2[j * 8 + 5] = *reinterpret_cast<__half2*>(&r5);
            rows2[j * 8 + 6] = *reinterpret_cast<__half2*>(&r6);
            rows2[j * 8 + 7] = *reinterpret_cast<__half2*>(&r7);
        }

        // initial v, replicated across the 16-lane group
        float v_own = vmean * (1.f / 72.f);
        float vv[16];
#pragma unroll
        for (int k = 0; k < 16; k++) vv[k] = __shfl_sync(FULL, v_own, k, 16);

        float ov = 0.f;
#pragma unroll
        for (int it = 0; it < 3; it++) {
            float sq = 0.f;
#pragma unroll
            for (int k = 0; k < 16; k++) sq = fmaf(vv[k], vv[k], sq);
            float rn = rsqrtf(fmaxf(sq, 1e-24f));

            float e[5];
#pragma unroll
            for (int j = 0; j < 5; j++) {
                float d = 0.f;
#pragma unroll
                for (int i = 0; i < 8; i++) {
                    float2 f = __half22float2(rows2[j * 8 + i]);
                    d = fmaf(f.x, vv[2 * i], d);
                    d = fmaf(f.y, vv[2 * i + 1], d);
                }
                e[j] = __expf(d * rn);
            }
            if (lane >= 8) e[4] = 0.f;

            float ssum = ((e[0] + e[1]) + (e[2] + e[3])) + e[4];
            ssum += __shfl_xor_sync(FULL, ssum, 8);
            ssum += __shfl_xor_sync(FULL, ssum, 4);
            ssum += __shfl_xor_sync(FULL, ssum, 2);
            ssum += __shfl_xor_sync(FULL, ssum, 1);

            float a[16];
#pragma unroll
            for (int i = 0; i < 8; i++) {
                float ax = 0.f, ay = 0.f;
#pragma unroll
                for (int j = 0; j < 5; j++) {
                    float2 f = __half22float2(rows2[j * 8 + i]);
                    ax = fmaf(e[j], f.x, ax);
                    ay = fmaf(e[j], f.y, ay);
                }
                a[2 * i] = ax;
                a[2 * i + 1] = ay;
            }

            // reduce-scatter: lane s ends with total a[s]
#pragma unroll
            for (int mm = 0; mm < 4; mm++) {
                const int m = 8 >> mm;
                bool up = (lane & m) != 0;
#pragma unroll
                for (int i = 0; i < 16; i++) {
                    if (i >= m) continue;
                    float send = up ? a[i] : a[i + m];
                    float got = __shfl_xor_sync(FULL, send, m);
                    a[i] = (up ? a[i + m] : a[i]) + got;
                }
            }
            float vfin = __fdividef(a[0], ssum);

            if (it < 2) {
#pragma unroll
                for (int k = 0; k < 16; k++) vv[k] = __shfl_sync(FULL, vfin, k, 16);
            } else {
                float s2 = vfin * vfin;
                s2 += __shfl_xor_sync(FULL, s2, 8);
                s2 += __shfl_xor_sync(FULL, s2, 4);
                s2 += __shfl_xor_sync(FULL, s2, 2);
                s2 += __shfl_xor_sync(FULL, s2, 1);
                float norm = sqrtf(s2);
                ov = vfin * __fdividef(norm, 1.f + s2);
            }
        }

        out[((b * 256 + col) * 32 + h) * 32 + w] = ov;
    }
}

extern "C" void kernel_launch(void* const* d_in, const int* in_sizes, int n_in,
                              void* d_out, int out_size) {
    const float* x = (const float*)d_in[0];    // [2,128,32,32]
    const float* w = (const float*)d_in[1];    // [16,16,16,3,3]
    float* out = (float*)d_out;                // [2,256,32,32]

    const int smem_bytes = 1152 * 4 + 72 * USTRIDE_P * 4;   // 4608 + 38016 = 42624 B
    cudaFuncSetAttribute(capsule_kernel,
                         cudaFuncAttributeMaxDynamicSharedMemorySize, smem_bytes);

    wt_transpose<<<36, 256>>>(w);
    capsule_kernel<<<2048, 128, smem_bytes>>>(x, out);
}

// round 10
// speedup vs baseline: 1.0970x; 1.0970x over previous
#include <cuda_runtime.h>
#include <cuda_fp16.h>
#include <float.h>
#include <math.h>

// CapsuleConv2d: B=2, Cin=128, H=W=32, weight [O=16,L=16,M=16,3,3]
// 1 CTA per (b,h,w), 128 threads, thread computes TWO columns: ol = tid, tid+128.
//  - priors (fp32 f32x2 FMA, split chains) streamed to smem as half2(sA,sB) pairs
//  - routing passes read the SAME pair rows; PRMT extracts lo (pass A) / hi (pass B)
//  - per-iter cross-lane: 4 + 15 + 16 shfl within 16-lane groups
//  - launch_bounds(128,3): spill-free (R9's forced 4-CTA cap spilled -> L2 27%)

__device__ float4 g_wT4[9 * 4 * 256];  // [(p*4+q)*256 + ol] = W[ol][4q..4q+3][p]

__global__ void wt_transpose(const float* __restrict__ w) {
    int idx = blockIdx.x * 256 + threadIdx.x;   // 9216 total
    int p  = idx >> 10;
    int q  = (idx >> 8) & 3;
    int ol = idx & 255;
    g_wT4[idx] = make_float4(w[(ol * 16 + 4 * q + 0) * 9 + p],
                             w[(ol * 16 + 4 * q + 1) * 9 + p],
                             w[(ol * 16 + 4 * q + 2) * 9 + p],
                             w[(ol * 16 + 4 * q + 3) * 9 + p]);
}

__device__ __forceinline__ unsigned long long fma2(unsigned long long a,
                                                   unsigned long long b,
                                                   unsigned long long c) {
    unsigned long long d;
    asm("fma.rn.f32x2 %0, %1, %2, %3;" : "=l"(d) : "l"(a), "l"(b), "l"(c));
    return d;
}
__device__ __forceinline__ unsigned long long add2(unsigned long long a,
                                                   unsigned long long b) {
    unsigned long long d;
    asm("add.rn.f32x2 %0, %1, %2;" : "=l"(d) : "l"(a), "l"(b));
    return d;
}
__device__ __forceinline__ unsigned prmt(unsigned a, unsigned b, unsigned sel) {
    unsigned d;
    asm("prmt.b32 %0, %1, %2, %3;" : "=r"(d) : "r"(a), "r"(b), "r"(sel));
    return d;
}

#define USTRIDE_P 132   // row stride in half2 pairs (528 B): conflict-free phases

__global__ __launch_bounds__(128, 3)
void capsule_kernel(const float* __restrict__ x, float* __restrict__ out) {
    extern __shared__ __align__(16) float smem[];
    float* xs = smem;                                      // 9*128 patch (fp32)
    unsigned* su = reinterpret_cast<unsigned*>(smem + 1152); // 72 * USTRIDE_P pairs

    const unsigned FULL = 0xffffffffu;
    const int tid = threadIdx.x;     // colA = tid, colB = tid + 128
    const int lane = tid & 15;       // l
    const int grp = tid >> 4;        // o for colA (0..7); colB is grp+8
    const int bid = blockIdx.x;
    const int b = bid >> 10;
    const int h = (bid >> 5) & 31;
    const int w = bid & 31;

    // Stage 3x3 patch (zero-padded): 9 pixels x 128 channels
    for (int idx = tid; idx < 9 * 128; idx += 128) {
        int p = idx >> 7;
        int c = idx & 127;
        int hh = h + p / 3 - 1;
        int ww = w + p % 3 - 1;
        float v = 0.f;
        if ((unsigned)hh < 32u && (unsigned)ww < 32u)
            v = x[((b * 128 + c) * 32 + hh) * 32 + ww];
        xs[idx] = v;
    }
    __syncthreads();

    // ---- priors for BOTH columns; split FMA chains per (p,g) ----
    float vmeanA = 0.f, vmeanB = 0.f;
    const ulonglong2* xs2 = reinterpret_cast<const ulonglong2*>(xs);
    const ulonglong2* wp = reinterpret_cast<const ulonglong2*>(g_wT4);
#pragma unroll
    for (int p = 0; p < 9; p++) {
        ulonglong2 wa0 = wp[(p * 4 + 0) * 256 + tid];
        ulonglong2 wa1 = wp[(p * 4 + 1) * 256 + tid];
        ulonglong2 wa2 = wp[(p * 4 + 2) * 256 + tid];
        ulonglong2 wa3 = wp[(p * 4 + 3) * 256 + tid];
        ulonglong2 wb0 = wp[(p * 4 + 0) * 256 + tid + 128];
        ulonglong2 wb1 = wp[(p * 4 + 1) * 256 + tid + 128];
        ulonglong2 wb2 = wp[(p * 4 + 2) * 256 + tid + 128];
        ulonglong2 wb3 = wp[(p * 4 + 3) * 256 + tid + 128];
#pragma unroll
        for (int g = 0; g < 8; g++) {
            ulonglong2 A  = xs2[p * 32 + g * 4 + 0];
            ulonglong2 Bq = xs2[p * 32 + g * 4 + 1];
            ulonglong2 C  = xs2[p * 32 + g * 4 + 2];
            ulonglong2 D  = xs2[p * 32 + g * 4 + 3];
            // two chains per column (even/odd 64-bit slices)
            unsigned long long a0 = fma2(A.x,  wa0.x, 0ull);
            unsigned long long a1 = fma2(A.y,  wa0.y, 0ull);
            unsigned long long b0 = fma2(A.x,  wb0.x, 0ull);
            unsigned long long b1 = fma2(A.y,  wb0.y, 0ull);
            a0 = fma2(Bq.x, wa1.x, a0);  a1 = fma2(Bq.y, wa1.y, a1);
            b0 = fma2(Bq.x, wb1.x, b0);  b1 = fma2(Bq.y, wb1.y, b1);
            a0 = fma2(C.x,  wa2.x, a0);  a1 = fma2(C.y,  wa2.y, a1);
            b0 = fma2(C.x,  wb2.x, b0);  b1 = fma2(C.y,  wb2.y, b1);
            a0 = fma2(D.x,  wa3.x, a0);  a1 = fma2(D.y,  wa3.y, a1);
            b0 = fma2(D.x,  wb3.x, b0);  b1 = fma2(D.y,  wb3.y, b1);
            unsigned long long sa = add2(a0, a1);
            unsigned long long sb = add2(b0, b1);
            float loA, hiA, loB, hiB;
            asm("mov.b64 {%0, %1}, %2;" : "=f"(loA), "=f"(hiA) : "l"(sa));
            asm("mov.b64 {%0, %1}, %2;" : "=f"(loB), "=f"(hiB) : "l"(sb));
            float sA = loA + hiA;
            float sB = loB + hiB;
            int n = g * 9 + p;
            __half2 pr = __floats2half2_rn(sA, sB);   // x = colA, y = colB
            su[n * USTRIDE_P + tid] = *reinterpret_cast<unsigned*>(&pr);
            vmeanA += sA;
            vmeanB += sB;
        }
    }
    __syncthreads();

    // ---- routing: two passes read SAME pair rows; PRMT selects lo/hi ----
#pragma unroll 1
    for (int pass = 0; pass < 2; pass++) {
        const int col = tid + pass * 128;
        const unsigned sel = pass ? 0x7632u : 0x5410u;   // hi : lo halves
        const float vmean = pass ? vmeanB : vmeanA;

        // rows2[j*8+i] = half2(u[16j+lane][colbase+2i], u[..][colbase+2i+1])
        __half2 rows2[40];
#pragma unroll
        for (int j = 0; j < 5; j++) {
            int n = 16 * j + lane;
            if (n >= 72) n -= 72;            // wrap; masked later (e4=0)
            const uint4* rp = reinterpret_cast<const uint4*>(su + n * USTRIDE_P + grp * 16);
            uint4 q0 = rp[0], q1 = rp[1], q2 = rp[2], q3 = rp[3];
            unsigned r0 = prmt(q0.x, q0.y, sel);
            unsigned r1 = prmt(q0.z, q0.w, sel);
            unsigned r2 = prmt(q1.x, q1.y, sel);
            unsigned r3 = prmt(q1.z, q1.w, sel);
            unsigned r4 = prmt(q2.x, q2.y, sel);
            unsigned r5 = prmt(q2.z, q2.w, sel);
            unsigned r6 = prmt(q3.x, q3.y, sel);
            unsigned r7 = prmt(q3.z, q3.w, sel);
            rows2[j * 8 + 0] = *reinterpret_cast<__half2*>(&r0);
            rows2[j * 8 + 1] = *reinterpret_cast<__half2*>(&r1);
            rows2[j * 8 + 2] = *reinterpret_cast<__half2*>(&r2);
            rows2[j * 8 + 3] = *reinterpret_cast<__half2*>(&r3);
            rows2[j * 8 + 4] = *reinterpret_cast<__half2*>(&r4);
            rows2[j * 8 + 5] = *reinterpret_cast<__half2*>(&r5);
            rows2[j * 8 + 6] = *reinterpret_cast<__half2*>(&r6);
            rows2[j * 8 + 7] = *reinterpret_cast<__half2*>(&r7);
        }

        // initial v, replicated across the 16-lane group
        float v_own = vmean * (1.f / 72.f);
        float vv[16];
#pragma unroll
        for (int k = 0; k < 16; k++) vv[k] = __shfl_sync(FULL, v_own, k, 16);

        float ov = 0.f;
#pragma unroll
        for (int it = 0; it < 3; it++) {
            float sq = 0.f;
#pragma unroll
            for (int k = 0; k < 16; k++) sq = fmaf(vv[k], vv[k], sq);
            float rn = rsqrtf(fmaxf(sq, 1e-24f));

            float e[5];
#pragma unroll
            for (int j = 0; j < 5; j++) {
                float d = 0.f;
#pragma unroll
                for (int i = 0; i < 8; i++) {
                    float2 f = __half22float2(rows2[j * 8 + i]);
                    d = fmaf(f.x, vv[2 * i], d);
                    d = fmaf(f.y, vv[2 * i + 1], d);
                }
                e[j] = __expf(d * rn);
            }
            if (lane >= 8) e[4] = 0.f;

            float ssum = ((e[0] + e[1]) + (e[2] + e[3])) + e[4];
            ssum += __shfl_xor_sync(FULL, ssum, 8);
            ssum += __shfl_xor_sync(FULL, ssum, 4);
            ssum += __shfl_xor_sync(FULL, ssum, 2);
            ssum += __shfl_xor_sync(FULL, ssum, 1);

            float a[16];
#pragma unroll
            for (int i = 0; i < 8; i++) {
                float ax = 0.f, ay = 0.f;
#pragma unroll
                for (int j = 0; j < 5; j++) {
                    float2 f = __half22float2(rows2[j * 8 + i]);
                    ax = fmaf(e[j], f.x, ax);
                    ay = fmaf(e[j], f.y, ay);
                }
                a[2 * i] = ax;
                a[2 * i + 1] = ay;
            }

            // reduce-scatter: lane s ends with total a[s]
#pragma unroll
            for (int mm = 0; mm < 4; mm++) {
                const int m = 8 >> mm;
                bool up = (lane & m) != 0;
#pragma unroll
                for (int i = 0; i < 16; i++) {
                    if (i >= m) continue;
                    float send = up ? a[i] : a[i + m];
                    float got = __shfl_xor_sync(FULL, send, m);
                    a[i] = (up ? a[i + m] : a[i]) + got;
                }
            }
            float vfin = __fdividef(a[0], ssum);

            if (it < 2) {
#pragma unroll
                for (int k = 0; k < 16; k++) vv[k] = __shfl_sync(FULL, vfin, k, 16);
            } else {
                float s2 = vfin * vfin;
                s2 += __shfl_xor_sync(FULL, s2, 8);
                s2 += __shfl_xor_sync(FULL, s2, 4);
                s2 += __shfl_xor_sync(FULL, s2, 2);
                s2 += __shfl_xor_sync(FULL, s2, 1);
                float norm = sqrtf(s2);
                ov = vfin * __fdividef(norm, 1.f + s2);
            }
        }

        out[((b * 256 + col) * 32 + h) * 32 + w] = ov;
    }
}

extern "C" void kernel_launch(void* const* d_in, const int* in_sizes, int n_in,
                              void* d_out, int out_size) {
    const float* x = (const float*)d_in[0];    // [2,128,32,32]
    const float* w = (const float*)d_in[1];    // [16,16,16,3,3]
    float* out = (float*)d_out;                // [2,256,32,32]

    const int smem_bytes = 1152 * 4 + 72 * USTRIDE_P * 4;   // 4608 + 38016 = 42624 B
    cudaFuncSetAttribute(capsule_kernel,
                         cudaFuncAttributeMaxDynamicSharedMemorySize, smem_bytes);

    wt_transpose<<<36, 256>>>(w);
    capsule_kernel<<<2048, 128, smem_bytes>>>(x, out);
}